// round 6
// baseline (speedup 1.0000x reference)
#include <cuda_runtime.h>
#include <math.h>

#define N_NODES 50000
#define N_EDGES 800000
#define F_IN    128
#define HID     64
#define H1      3
#define D1      (H1*HID)        // 192
#define OUT     64
#define LRELU   0.2f
#define NBLK    ((N_NODES + 255) / 256)   // 196

// ---------------- scratch (device globals; no allocation allowed) ----------------
__device__ int   g_is64;
__device__ int   g_src[N_EDGES];
__device__ int   g_dst[N_EDGES];
__device__ int   g_cnt[N_NODES];
__device__ int   g_bsum[256];
__device__ int   g_boff[256];
__device__ int   g_rowoff[N_NODES + 1];
__device__ int   g_cur[N_NODES];
__device__ int   g_esrc[N_EDGES];
__device__ float g_ea[N_EDGES];
__device__ float g_xw1[(size_t)N_NODES * 384];  // [node][xl(192) | xr(192)]
__device__ float g_h1[(size_t)N_NODES * D1];
__device__ float g_xw2[(size_t)N_NODES * 128];  // [node][xl(64) | xr(64)]

// ---------------- helpers ----------------
__device__ __forceinline__ float lrelu(float v) { return v > 0.f ? v : LRELU * v; }
__device__ __forceinline__ float elu(float v)   { return v > 0.f ? v : expm1f(v); }

// ---------------- edge_index dtype detect ----------------
__global__ void detect_kernel(const int* __restrict__ p) {
    int acc = 0;
    for (int i = threadIdx.x; i < 2048; i += blockDim.x) acc |= p[2 * i + 1];
    int any = __syncthreads_or(acc);
    if (threadIdx.x == 0) g_is64 = (any == 0) ? 1 : 0;
}

__global__ void clear_cnt() {
    int i = blockIdx.x * blockDim.x + threadIdx.x;
    if (i < N_NODES) g_cnt[i] = 0;
}

// convert + histogram in one pass
__global__ void convert_hist(const int* __restrict__ p) {
    int i = blockIdx.x * blockDim.x + threadIdx.x;
    if (i >= N_EDGES) return;
    int s, d;
    if (g_is64) {
        s = p[2 * i];
        d = p[2 * N_EDGES + 2 * i];
    } else {
        s = p[i];
        d = p[N_EDGES + i];
    }
    g_src[i] = s;
    g_dst[i] = d;
    atomicAdd(&g_cnt[d], 1);
}

__global__ void scanA() {   // per-block sums of g_cnt
    __shared__ int sm[256];
    int i = blockIdx.x * 256 + threadIdx.x;
    sm[threadIdx.x] = (i < N_NODES) ? g_cnt[i] : 0;
    __syncthreads();
    for (int off = 128; off; off >>= 1) {
        if (threadIdx.x < off) sm[threadIdx.x] += sm[threadIdx.x + off];
        __syncthreads();
    }
    if (threadIdx.x == 0) g_bsum[blockIdx.x] = sm[0];
}

__global__ void scanB() {   // exclusive scan of block sums (single block)
    __shared__ int sm[256];
    int t = threadIdx.x;
    sm[t] = (t < NBLK) ? g_bsum[t] : 0;
    __syncthreads();
    for (int off = 1; off < 256; off <<= 1) {
        int v = (t >= off) ? sm[t - off] : 0;
        __syncthreads();
        sm[t] += v;
        __syncthreads();
    }
    if (t < NBLK) g_boff[t] = sm[t] - g_bsum[t];  // exclusive
}

__global__ void scanC() {   // local exclusive scan + block offset -> rowoff, cur
    __shared__ int sm[256];
    int t = threadIdx.x;
    int i = blockIdx.x * 256 + t;
    int c = (i < N_NODES) ? g_cnt[i] : 0;
    sm[t] = c;
    __syncthreads();
    for (int off = 1; off < 256; off <<= 1) {
        int v = (t >= off) ? sm[t - off] : 0;
        __syncthreads();
        sm[t] += v;
        __syncthreads();
    }
    if (i < N_NODES) {
        int start = g_boff[blockIdx.x] + sm[t] - c;
        g_rowoff[i] = start;
        g_cur[i] = start;
    }
    if (blockIdx.x == 0 && t == 0) g_rowoff[N_NODES] = N_EDGES;
}

__global__ void scatter_kernel(const float* __restrict__ eattr) {
    int e = blockIdx.x * blockDim.x + threadIdx.x;
    if (e >= N_EDGES) return;
    int d = g_dst[e];
    int pos = atomicAdd(&g_cur[d], 1);
    g_esrc[pos] = g_src[e];
    g_ea[pos]   = eattr[e];
}

// ---------------- SGEMM: C[M,2*halfN] = A @ [B1|B2] + [bias1|bias2] ------------
// BM=BN=128, BK=8, 256 threads, 8x8 micro-tile, double-buffered smem.
__global__ __launch_bounds__(256, 2) void sgemm2(
    const float* __restrict__ A,
    const float* __restrict__ B1, const float* __restrict__ B2,
    const float* __restrict__ bias1, const float* __restrict__ bias2,
    float* __restrict__ C, int M, int K, int halfN)
{
    __shared__ float As[2][8][128];
    __shared__ float Bs[2][8][128];
    const int N = 2 * halfN;
    int tid = threadIdx.x;
    int row0 = blockIdx.y * 128, col0 = blockIdx.x * 128;

    int aRow = tid >> 1, aCol = (tid & 1) * 4;
    int bRow = tid >> 5, bCol = (tid & 31) * 4;
    int gcol = col0 + bCol;
    const float* Bsrc = (gcol < halfN) ? B1 : B2;
    int bc = (gcol < halfN) ? gcol : gcol - halfN;

    int tx = tid & 15, ty = tid >> 4;
    float acc[8][8] = {};

    float4 av, bv;
    {
        int r = row0 + aRow;
        av = (r < M) ? *(const float4*)(A + (size_t)r * K + aCol)
                     : make_float4(0.f, 0.f, 0.f, 0.f);
        bv = *(const float4*)(Bsrc + (size_t)bRow * halfN + bc);
        As[0][aCol + 0][aRow] = av.x; As[0][aCol + 1][aRow] = av.y;
        As[0][aCol + 2][aRow] = av.z; As[0][aCol + 3][aRow] = av.w;
        *(float4*)&Bs[0][bRow][bCol] = bv;
    }
    __syncthreads();

    int nk = K / 8;
    for (int kt = 0; kt < nk; kt++) {
        int buf = kt & 1;
        if (kt + 1 < nk) {
            int k0 = (kt + 1) * 8;
            int r = row0 + aRow;
            av = (r < M) ? *(const float4*)(A + (size_t)r * K + k0 + aCol)
                         : make_float4(0.f, 0.f, 0.f, 0.f);
            bv = *(const float4*)(Bsrc + (size_t)(k0 + bRow) * halfN + bc);
        }
#pragma unroll
        for (int k = 0; k < 8; k++) {
            float4 a0 = *(const float4*)&As[buf][k][ty * 4];
            float4 a1 = *(const float4*)&As[buf][k][ty * 4 + 64];
            float4 b0 = *(const float4*)&Bs[buf][k][tx * 4];
            float4 b1 = *(const float4*)&Bs[buf][k][tx * 4 + 64];
            float ar[8] = {a0.x, a0.y, a0.z, a0.w, a1.x, a1.y, a1.z, a1.w};
            float br[8] = {b0.x, b0.y, b0.z, b0.w, b1.x, b1.y, b1.z, b1.w};
#pragma unroll
            for (int i = 0; i < 8; i++)
#pragma unroll
                for (int j = 0; j < 8; j++) acc[i][j] += ar[i] * br[j];
        }
        if (kt + 1 < nk) {
            int nb = buf ^ 1;
            As[nb][aCol + 0][aRow] = av.x; As[nb][aCol + 1][aRow] = av.y;
            As[nb][aCol + 2][aRow] = av.z; As[nb][aCol + 3][aRow] = av.w;
            *(float4*)&Bs[nb][bRow][bCol] = bv;
        }
        __syncthreads();
    }

    float bsv[8];
#pragma unroll
    for (int j = 0; j < 8; j++) {
        int c = col0 + ((j < 4) ? tx * 4 + j : 64 + tx * 4 + (j - 4));
        bsv[j] = (c < halfN) ? bias1[c] : bias2[c - halfN];
    }
#pragma unroll
    for (int i = 0; i < 8; i++) {
        int r = row0 + ((i < 4) ? ty * 4 + i : 64 + ty * 4 + (i - 4));
        if (r >= M) continue;
        float4 v0 = make_float4(acc[i][0] + bsv[0], acc[i][1] + bsv[1],
                                acc[i][2] + bsv[2], acc[i][3] + bsv[3]);
        float4 v1 = make_float4(acc[i][4] + bsv[4], acc[i][5] + bsv[5],
                                acc[i][6] + bsv[6], acc[i][7] + bsv[7]);
        *(float4*)(C + (size_t)r * N + col0 + tx * 4)      = v0;
        *(float4*)(C + (size_t)r * N + col0 + 64 + tx * 4) = v1;
    }
}

// ---------------- SGEMM half-height: BM=64, BN=128 (for the N=128 GEMM tail) ----
__global__ __launch_bounds__(256) void sgemm2h(
    const float* __restrict__ A,
    const float* __restrict__ B1, const float* __restrict__ B2,
    const float* __restrict__ bias1, const float* __restrict__ bias2,
    float* __restrict__ C, int M, int K, int halfN)
{
    __shared__ float As[2][8][64];
    __shared__ float Bs[2][8][128];
    const int N = 2 * halfN;
    int tid = threadIdx.x;
    int row0 = blockIdx.y * 64, col0 = blockIdx.x * 128;

    int aRow = tid >> 2, aCol = (tid & 3) * 2;
    int bRow = tid >> 5, bCol = (tid & 31) * 4;
    int gcol = col0 + bCol;
    const float* Bsrc = (gcol < halfN) ? B1 : B2;
    int bc = (gcol < halfN) ? gcol : gcol - halfN;

    int tx = tid & 15, ty = tid >> 4;   // ty 0..15
    float acc[4][8] = {};

    float2 av; float4 bv;
    {
        int r = row0 + aRow;
        av = (r < M) ? *(const float2*)(A + (size_t)r * K + aCol)
                     : make_float2(0.f, 0.f);
        bv = *(const float4*)(Bsrc + (size_t)bRow * halfN + bc);
        As[0][aCol + 0][aRow] = av.x; As[0][aCol + 1][aRow] = av.y;
        *(float4*)&Bs[0][bRow][bCol] = bv;
    }
    __syncthreads();

    int nk = K / 8;
    for (int kt = 0; kt < nk; kt++) {
        int buf = kt & 1;
        if (kt + 1 < nk) {
            int k0 = (kt + 1) * 8;
            int r = row0 + aRow;
            av = (r < M) ? *(const float2*)(A + (size_t)r * K + k0 + aCol)
                         : make_float2(0.f, 0.f);
            bv = *(const float4*)(Bsrc + (size_t)(k0 + bRow) * halfN + bc);
        }
#pragma unroll
        for (int k = 0; k < 8; k++) {
            float2 a0 = *(const float2*)&As[buf][k][ty * 2];
            float2 a1 = *(const float2*)&As[buf][k][ty * 2 + 32];
            float4 b0 = *(const float4*)&Bs[buf][k][tx * 4];
            float4 b1 = *(const float4*)&Bs[buf][k][tx * 4 + 64];
            float ar[4] = {a0.x, a0.y, a1.x, a1.y};
            float br[8] = {b0.x, b0.y, b0.z, b0.w, b1.x, b1.y, b1.z, b1.w};
#pragma unroll
            for (int i = 0; i < 4; i++)
#pragma unroll
                for (int j = 0; j < 8; j++) acc[i][j] += ar[i] * br[j];
        }
        if (kt + 1 < nk) {
            int nb = buf ^ 1;
            As[nb][aCol + 0][aRow] = av.x; As[nb][aCol + 1][aRow] = av.y;
            *(float4*)&Bs[nb][bRow][bCol] = bv;
        }
        __syncthreads();
    }

    float bsv[8];
#pragma unroll
    for (int j = 0; j < 8; j++) {
        int c = col0 + ((j < 4) ? tx * 4 + j : 64 + tx * 4 + (j - 4));
        bsv[j] = (c < halfN) ? bias1[c] : bias2[c - halfN];
    }
    const int rofs[4] = {ty * 2, ty * 2 + 1, ty * 2 + 32, ty * 2 + 33};
#pragma unroll
    for (int i = 0; i < 4; i++) {
        int r = row0 + rofs[i];
        if (r >= M) continue;
        float4 v0 = make_float4(acc[i][0] + bsv[0], acc[i][1] + bsv[1],
                                acc[i][2] + bsv[2], acc[i][3] + bsv[3]);
        float4 v1 = make_float4(acc[i][4] + bsv[4], acc[i][5] + bsv[5],
                                acc[i][6] + bsv[6], acc[i][7] + bsv[7]);
        *(float4*)(C + (size_t)r * N + col0 + tx * 4)      = v0;
        *(float4*)(C + (size_t)r * N + col0 + 64 + tx * 4) = v1;
    }
}

// ---------------- fused GAT layer 1: warp/node, 24 lanes x 8 ch, pipelined ------
// 2-stage software pipeline: edge index prefetched 2 ahead, feature vectors 1
// ahead, so the gather latency is overlapped with the previous edge's compute.
__global__ __launch_bounds__(256) void gat1_kernel(
    const float* __restrict__ We, const float* __restrict__ att,
    const float* __restrict__ bias)
{
    int node = blockIdx.x * 8 + (threadIdx.x >> 5);
    int lane = threadIdx.x & 31;
    if (node >= N_NODES) return;
    int beg = g_rowoff[node];
    int cnt = g_rowoff[node + 1] - beg;
    int chb = (lane < 24) ? (lane << 3) : 0;

    const float4* xrp = (const float4*)(g_xw1 + (size_t)node * 384 + 192 + chb);
    float4 xr0 = xrp[0], xr1 = xrp[1];
    float4 We0 = *(const float4*)(We + chb),  We4 = *(const float4*)(We + chb + 4);
    float4 at0 = *(const float4*)(att + chb), at4 = *(const float4*)(att + chb + 4);

    float4 acc0 = make_float4(0.f, 0.f, 0.f, 0.f);
    float4 acc1 = make_float4(0.f, 0.f, 0.f, 0.f);
    float den = 0.f;

    // pipeline state: (a0, x0a/x0b) = edge i;  (s1, a1) = edge i+1
    int s1 = 0; float a0 = 0.f, a1 = 0.f;
    float4 x0a = make_float4(0.f, 0.f, 0.f, 0.f), x0b = x0a;
    if (cnt > 0) {
        int s0 = g_esrc[beg]; a0 = g_ea[beg];
        const float4* p = (const float4*)(g_xw1 + (size_t)s0 * 384 + chb);
        x0a = p[0]; x0b = p[1];
    }
    if (cnt > 1) { s1 = g_esrc[beg + 1]; a1 = g_ea[beg + 1]; }

    for (int i = 0; i < cnt; i++) {
        // prefetch edge index i+2
        int sn = 0; float an = 0.f;
        if (i + 2 < cnt) { sn = g_esrc[beg + i + 2]; an = g_ea[beg + i + 2]; }
        // prefetch features of edge i+1 (issued before compute; consumed next iter)
        float4 x1a = x0a, x1b = x0b;
        if (i + 1 < cnt) {
            const float4* p = (const float4*)(g_xw1 + (size_t)s1 * 384 + chb);
            x1a = p[0]; x1b = p[1];
        }

        float p;
        p  = at0.x * lrelu(fmaf(a0, We0.x, x0a.x + xr0.x));
        p += at0.y * lrelu(fmaf(a0, We0.y, x0a.y + xr0.y));
        p += at0.z * lrelu(fmaf(a0, We0.z, x0a.z + xr0.z));
        p += at0.w * lrelu(fmaf(a0, We0.w, x0a.w + xr0.w));
        p += at4.x * lrelu(fmaf(a0, We4.x, x0b.x + xr1.x));
        p += at4.y * lrelu(fmaf(a0, We4.y, x0b.y + xr1.y));
        p += at4.z * lrelu(fmaf(a0, We4.z, x0b.z + xr1.z));
        p += at4.w * lrelu(fmaf(a0, We4.w, x0b.w + xr1.w));
        // head-group (8 lanes) butterfly
        p += __shfl_xor_sync(0xffffffffu, p, 1);
        p += __shfl_xor_sync(0xffffffffu, p, 2);
        p += __shfl_xor_sync(0xffffffffu, p, 4);
        float w = __expf(p);
        den += w;
        acc0.x = fmaf(w, x0a.x, acc0.x); acc0.y = fmaf(w, x0a.y, acc0.y);
        acc0.z = fmaf(w, x0a.z, acc0.z); acc0.w = fmaf(w, x0a.w, acc0.w);
        acc1.x = fmaf(w, x0b.x, acc1.x); acc1.y = fmaf(w, x0b.y, acc1.y);
        acc1.z = fmaf(w, x0b.z, acc1.z); acc1.w = fmaf(w, x0b.w, acc1.w);

        x0a = x1a; x0b = x1b; a0 = a1; s1 = sn; a1 = an;
    }

    if (lane < 24) {
        float dinv = 1.f / (den + 1e-16f);
        float4 b0 = *(const float4*)(bias + chb);
        float4 b4 = *(const float4*)(bias + chb + 4);
        float4 o0, o1;
        o0.x = elu(fmaf(acc0.x, dinv, b0.x));
        o0.y = elu(fmaf(acc0.y, dinv, b0.y));
        o0.z = elu(fmaf(acc0.z, dinv, b0.z));
        o0.w = elu(fmaf(acc0.w, dinv, b0.w));
        o1.x = elu(fmaf(acc1.x, dinv, b4.x));
        o1.y = elu(fmaf(acc1.y, dinv, b4.y));
        o1.z = elu(fmaf(acc1.z, dinv, b4.z));
        o1.w = elu(fmaf(acc1.w, dinv, b4.w));
        float4* hp = (float4*)(g_h1 + (size_t)node * D1 + chb);
        hp[0] = o0; hp[1] = o1;
    }
}

// ---------------- fused GAT layer 2: warp/node, 4 edges/warp, 8 lanes x 8 ch ----
// Pipelined like gat1. Groups: lane>>3 -> edge base+grp. Logit butterfly within
// 8-lane group; accumulators combined across groups once at the end.
__global__ __launch_bounds__(256) void gat2_kernel(
    const float* __restrict__ We, const float* __restrict__ att,
    const float* __restrict__ bias, float* __restrict__ out)
{
    int node = blockIdx.x * 8 + (threadIdx.x >> 5);
    int lane = threadIdx.x & 31;
    if (node >= N_NODES) return;
    int beg = g_rowoff[node];
    int end = g_rowoff[node + 1];
    int grp = lane >> 3;
    int chb = (lane & 7) << 3;

    const float4* xrp = (const float4*)(g_xw2 + (size_t)node * 128 + 64 + chb);
    float4 xr0 = xrp[0], xr1 = xrp[1];
    float4 We0 = *(const float4*)(We + chb),  We4 = *(const float4*)(We + chb + 4);
    float4 at0 = *(const float4*)(att + chb), at4 = *(const float4*)(att + chb + 4);

    float4 acc0 = make_float4(0.f, 0.f, 0.f, 0.f);
    float4 acc1 = make_float4(0.f, 0.f, 0.f, 0.f);
    float den = 0.f;

    int base = beg;
    // pipeline state: edge e0 = base+grp (v0,a0,x0*); edge e1 = base+4+grp (s1,a1,v1)
    bool v0 = (beg + grp) < end;
    bool v1 = (beg + 4 + grp) < end;
    int s1 = 0; float a0 = 0.f, a1 = 0.f;
    float4 x0a = make_float4(0.f, 0.f, 0.f, 0.f), x0b = x0a;
    if (v0) {
        int s0 = g_esrc[beg + grp]; a0 = g_ea[beg + grp];
        const float4* p = (const float4*)(g_xw2 + (size_t)s0 * 128 + chb);
        x0a = p[0]; x0b = p[1];
    }
    if (v1) { s1 = g_esrc[beg + 4 + grp]; a1 = g_ea[beg + 4 + grp]; }

    while (base < end) {
        // prefetch edge index base+8+grp
        int en = base + 8 + grp;
        bool vn = en < end;
        int sn = 0; float an = 0.f;
        if (vn) { sn = g_esrc[en]; an = g_ea[en]; }
        // prefetch features of edge base+4+grp
        float4 x1a = x0a, x1b = x0b;
        if (v1) {
            const float4* p = (const float4*)(g_xw2 + (size_t)s1 * 128 + chb);
            x1a = p[0]; x1b = p[1];
        }

        float p;
        p  = at0.x * lrelu(fmaf(a0, We0.x, x0a.x + xr0.x));
        p += at0.y * lrelu(fmaf(a0, We0.y, x0a.y + xr0.y));
        p += at0.z * lrelu(fmaf(a0, We0.z, x0a.z + xr0.z));
        p += at0.w * lrelu(fmaf(a0, We0.w, x0a.w + xr0.w));
        p += at4.x * lrelu(fmaf(a0, We4.x, x0b.x + xr1.x));
        p += at4.y * lrelu(fmaf(a0, We4.y, x0b.y + xr1.y));
        p += at4.z * lrelu(fmaf(a0, We4.z, x0b.z + xr1.z));
        p += at4.w * lrelu(fmaf(a0, We4.w, x0b.w + xr1.w));
        // butterfly within 8-lane group
        p += __shfl_xor_sync(0xffffffffu, p, 1);
        p += __shfl_xor_sync(0xffffffffu, p, 2);
        p += __shfl_xor_sync(0xffffffffu, p, 4);
        float w = v0 ? __expf(p) : 0.f;
        den += w;
        acc0.x = fmaf(w, x0a.x, acc0.x); acc0.y = fmaf(w, x0a.y, acc0.y);
        acc0.z = fmaf(w, x0a.z, acc0.z); acc0.w = fmaf(w, x0a.w, acc0.w);
        acc1.x = fmaf(w, x0b.x, acc1.x); acc1.y = fmaf(w, x0b.y, acc1.y);
        acc1.z = fmaf(w, x0b.z, acc1.z); acc1.w = fmaf(w, x0b.w, acc1.w);

        x0a = x1a; x0b = x1b; a0 = a1; v0 = v1; s1 = sn; a1 = an; v1 = vn;
        base += 4;
    }

    // combine the 4 groups (same channel on lane, lane^8, lane^16, lane^24)
#pragma unroll
    for (int off = 8; off <= 16; off <<= 1) {
        den    += __shfl_xor_sync(0xffffffffu, den,    off);
        acc0.x += __shfl_xor_sync(0xffffffffu, acc0.x, off);
        acc0.y += __shfl_xor_sync(0xffffffffu, acc0.y, off);
        acc0.z += __shfl_xor_sync(0xffffffffu, acc0.z, off);
        acc0.w += __shfl_xor_sync(0xffffffffu, acc0.w, off);
        acc1.x += __shfl_xor_sync(0xffffffffu, acc1.x, off);
        acc1.y += __shfl_xor_sync(0xffffffffu, acc1.y, off);
        acc1.z += __shfl_xor_sync(0xffffffffu, acc1.z, off);
        acc1.w += __shfl_xor_sync(0xffffffffu, acc1.w, off);
    }

    if (grp == 0) {
        float dinv = 1.f / (den + 1e-16f);
        float4 b0 = *(const float4*)(bias + chb);
        float4 b4 = *(const float4*)(bias + chb + 4);
        float4 o0, o1;
        o0.x = elu(fmaf(acc0.x, dinv, b0.x));
        o0.y = elu(fmaf(acc0.y, dinv, b0.y));
        o0.z = elu(fmaf(acc0.z, dinv, b0.z));
        o0.w = elu(fmaf(acc0.w, dinv, b0.w));
        o1.x = elu(fmaf(acc1.x, dinv, b4.x));
        o1.y = elu(fmaf(acc1.y, dinv, b4.y));
        o1.z = elu(fmaf(acc1.z, dinv, b4.z));
        o1.w = elu(fmaf(acc1.w, dinv, b4.w));
        float4* op = (float4*)(out + (size_t)node * OUT + chb);
        op[0] = o0; op[1] = o1;
    }
}

// ---------------- launch ----------------
extern "C" void kernel_launch(void* const* d_in, const int* in_sizes, int n_in,
                              void* d_out, int out_size) {
    const float* x     = (const float*)d_in[0];
    const int*   eidx  = (const int*)d_in[1];
    const float* eattr = (const float*)d_in[2];
    const float* Wl1   = (const float*)d_in[3];
    const float* bl1   = (const float*)d_in[4];
    const float* Wr1   = (const float*)d_in[5];
    const float* br1   = (const float*)d_in[6];
    const float* We1   = (const float*)d_in[7];
    const float* att1  = (const float*)d_in[8];
    const float* bias1 = (const float*)d_in[9];
    const float* Wl2   = (const float*)d_in[10];
    const float* bl2   = (const float*)d_in[11];
    const float* Wr2   = (const float*)d_in[12];
    const float* br2   = (const float*)d_in[13];
    const float* We2   = (const float*)d_in[14];
    const float* att2  = (const float*)d_in[15];
    const float* bias2 = (const float*)d_in[16];
    float* out = (float*)d_out;

    static float* p_xw1 = nullptr;
    static float* p_h1  = nullptr;
    static float* p_xw2 = nullptr;
    if (!p_xw1) {
        cudaGetSymbolAddress((void**)&p_xw1, g_xw1);
        cudaGetSymbolAddress((void**)&p_h1,  g_h1);
        cudaGetSymbolAddress((void**)&p_xw2, g_xw2);
    }

    const int ET = (N_EDGES + 255) / 256;

    // CSR build
    detect_kernel<<<1, 256>>>(eidx);
    clear_cnt<<<NBLK, 256>>>();
    convert_hist<<<ET, 256>>>(eidx);
    scanA<<<NBLK, 256>>>();
    scanB<<<1, 256>>>();
    scanC<<<NBLK, 256>>>();
    scatter_kernel<<<ET, 256>>>(eattr);

    // layer 1: xw1 = x @ [Wl1|Wr1] + [bl1|br1]   (N = 384)
    {
        dim3 grid(3, (N_NODES + 127) / 128);
        sgemm2<<<grid, 256>>>(x, Wl1, Wr1, bl1, br1, p_xw1, N_NODES, F_IN, D1);
    }
    gat1_kernel<<<(N_NODES + 7) / 8, 256>>>(We1, att1, bias1);

    // layer 2: xw2 = h1 @ [Wl2|Wr2] + [bl2|br2]  (N = 128), BM=64 tiles
    {
        dim3 grid(1, (N_NODES + 63) / 64);
        sgemm2h<<<grid, 256>>>(p_h1, Wl2, Wr2, bl2, br2, p_xw2, N_NODES, D1, OUT);
    }
    gat2_kernel<<<(N_NODES + 7) / 8, 256>>>(We2, att2, bias2, out);
}

// round 11
// speedup vs baseline: 1.0284x; 1.0284x over previous
#include <cuda_runtime.h>
#include <math.h>

#define N_NODES 50000
#define N_EDGES 800000
#define F_IN    128
#define HID     64
#define H1      3
#define D1      (H1*HID)        // 192
#define OUT     64
#define LRELU   0.2f
#define NBLK    ((N_NODES + 255) / 256)   // 196

// ---------------- scratch (device globals; no allocation allowed) ----------------
__device__ int   g_is64;
__device__ int   g_cnt[N_NODES];
__device__ int   g_bsum[256];
__device__ int   g_boff[256];
__device__ int   g_rowoff[N_NODES + 1];
__device__ int   g_cur[N_NODES];
__device__ int2  g_epack[N_EDGES];              // {src, float_bits(edge_attr)}
__device__ float g_xw1[(size_t)N_NODES * 384];  // [node][xl(192) | xr(192)]
__device__ float g_h1[(size_t)N_NODES * D1];
__device__ float g_xw2[(size_t)N_NODES * 128];  // [node][xl(64) | xr(64)]

// ---------------- helpers ----------------
__device__ __forceinline__ float lrelu(float v) { return v > 0.f ? v : LRELU * v; }
__device__ __forceinline__ float elu(float v)   { return v > 0.f ? v : expm1f(v); }

// ---------------- edge_index dtype detect ----------------
__global__ void detect_kernel(const int* __restrict__ p) {
    int acc = 0;
    for (int i = threadIdx.x; i < 2048; i += blockDim.x) acc |= p[2 * i + 1];
    int any = __syncthreads_or(acc);
    if (threadIdx.x == 0) g_is64 = (any == 0) ? 1 : 0;
}

__global__ void clear_cnt() {
    int i = blockIdx.x * blockDim.x + threadIdx.x;
    if (i < N_NODES) g_cnt[i] = 0;
}

// histogram of dst (reads edge_index directly)
__global__ void hist_kernel(const int* __restrict__ p) {
    int i = blockIdx.x * blockDim.x + threadIdx.x;
    if (i >= N_EDGES) return;
    int d = g_is64 ? p[2 * N_EDGES + 2 * i] : p[N_EDGES + i];
    atomicAdd(&g_cnt[d], 1);
}

__global__ void scanA() {   // per-block sums of g_cnt
    __shared__ int sm[256];
    int i = blockIdx.x * 256 + threadIdx.x;
    sm[threadIdx.x] = (i < N_NODES) ? g_cnt[i] : 0;
    __syncthreads();
    for (int off = 128; off; off >>= 1) {
        if (threadIdx.x < off) sm[threadIdx.x] += sm[threadIdx.x + off];
        __syncthreads();
    }
    if (threadIdx.x == 0) g_bsum[blockIdx.x] = sm[0];
}

__global__ void scanB() {   // exclusive scan of block sums (single block)
    __shared__ int sm[256];
    int t = threadIdx.x;
    sm[t] = (t < NBLK) ? g_bsum[t] : 0;
    __syncthreads();
    for (int off = 1; off < 256; off <<= 1) {
        int v = (t >= off) ? sm[t - off] : 0;
        __syncthreads();
        sm[t] += v;
        __syncthreads();
    }
    if (t < NBLK) g_boff[t] = sm[t] - g_bsum[t];  // exclusive
}

__global__ void scanC() {   // local exclusive scan + block offset -> rowoff, cur
    __shared__ int sm[256];
    int t = threadIdx.x;
    int i = blockIdx.x * 256 + t;
    int c = (i < N_NODES) ? g_cnt[i] : 0;
    sm[t] = c;
    __syncthreads();
    for (int off = 1; off < 256; off <<= 1) {
        int v = (t >= off) ? sm[t - off] : 0;
        __syncthreads();
        sm[t] += v;
        __syncthreads();
    }
    if (i < N_NODES) {
        int start = g_boff[blockIdx.x] + sm[t] - c;
        g_rowoff[i] = start;
        g_cur[i] = start;
    }
    if (blockIdx.x == 0 && t == 0) g_rowoff[N_NODES] = N_EDGES;
}

// CSR scatter: reads edge_index + eattr directly, writes packed {src, ea}
__global__ void scatter_kernel(const int* __restrict__ p,
                               const float* __restrict__ eattr) {
    int i = blockIdx.x * blockDim.x + threadIdx.x;
    if (i >= N_EDGES) return;
    int s, d;
    if (g_is64) {
        s = p[2 * i];
        d = p[2 * N_EDGES + 2 * i];
    } else {
        s = p[i];
        d = p[N_EDGES + i];
    }
    int pos = atomicAdd(&g_cur[d], 1);
    g_epack[pos] = make_int2(s, __float_as_int(eattr[i]));
}

// ---------------- SGEMM: C[M,2*halfN] = A @ [B1|B2] + [bias1|bias2] ------------
// BM=BN=128, BK=8, 256 threads, 8x8 micro-tile, double-buffered smem.
__global__ __launch_bounds__(256, 2) void sgemm2(
    const float* __restrict__ A,
    const float* __restrict__ B1, const float* __restrict__ B2,
    const float* __restrict__ bias1, const float* __restrict__ bias2,
    float* __restrict__ C, int M, int K, int halfN)
{
    __shared__ float As[2][8][128];
    __shared__ float Bs[2][8][128];
    const int N = 2 * halfN;
    int tid = threadIdx.x;
    int row0 = blockIdx.y * 128, col0 = blockIdx.x * 128;

    int aRow = tid >> 1, aCol = (tid & 1) * 4;
    int bRow = tid >> 5, bCol = (tid & 31) * 4;
    int gcol = col0 + bCol;
    const float* Bsrc = (gcol < halfN) ? B1 : B2;
    int bc = (gcol < halfN) ? gcol : gcol - halfN;

    int tx = tid & 15, ty = tid >> 4;
    float acc[8][8] = {};

    float4 av, bv;
    {
        int r = row0 + aRow;
        av = (r < M) ? *(const float4*)(A + (size_t)r * K + aCol)
                     : make_float4(0.f, 0.f, 0.f, 0.f);
        bv = *(const float4*)(Bsrc + (size_t)bRow * halfN + bc);
        As[0][aCol + 0][aRow] = av.x; As[0][aCol + 1][aRow] = av.y;
        As[0][aCol + 2][aRow] = av.z; As[0][aCol + 3][aRow] = av.w;
        *(float4*)&Bs[0][bRow][bCol] = bv;
    }
    __syncthreads();

    int nk = K / 8;
    for (int kt = 0; kt < nk; kt++) {
        int buf = kt & 1;
        if (kt + 1 < nk) {
            int k0 = (kt + 1) * 8;
            int r = row0 + aRow;
            av = (r < M) ? *(const float4*)(A + (size_t)r * K + k0 + aCol)
                         : make_float4(0.f, 0.f, 0.f, 0.f);
            bv = *(const float4*)(Bsrc + (size_t)(k0 + bRow) * halfN + bc);
        }
#pragma unroll
        for (int k = 0; k < 8; k++) {
            float4 a0 = *(const float4*)&As[buf][k][ty * 4];
            float4 a1 = *(const float4*)&As[buf][k][ty * 4 + 64];
            float4 b0 = *(const float4*)&Bs[buf][k][tx * 4];
            float4 b1 = *(const float4*)&Bs[buf][k][tx * 4 + 64];
            float ar[8] = {a0.x, a0.y, a0.z, a0.w, a1.x, a1.y, a1.z, a1.w};
            float br[8] = {b0.x, b0.y, b0.z, b0.w, b1.x, b1.y, b1.z, b1.w};
#pragma unroll
            for (int i = 0; i < 8; i++)
#pragma unroll
                for (int j = 0; j < 8; j++) acc[i][j] += ar[i] * br[j];
        }
        if (kt + 1 < nk) {
            int nb = buf ^ 1;
            As[nb][aCol + 0][aRow] = av.x; As[nb][aCol + 1][aRow] = av.y;
            As[nb][aCol + 2][aRow] = av.z; As[nb][aCol + 3][aRow] = av.w;
            *(float4*)&Bs[nb][bRow][bCol] = bv;
        }
        __syncthreads();
    }

    float bsv[8];
#pragma unroll
    for (int j = 0; j < 8; j++) {
        int c = col0 + ((j < 4) ? tx * 4 + j : 64 + tx * 4 + (j - 4));
        bsv[j] = (c < halfN) ? bias1[c] : bias2[c - halfN];
    }
#pragma unroll
    for (int i = 0; i < 8; i++) {
        int r = row0 + ((i < 4) ? ty * 4 + i : 64 + ty * 4 + (i - 4));
        if (r >= M) continue;
        float4 v0 = make_float4(acc[i][0] + bsv[0], acc[i][1] + bsv[1],
                                acc[i][2] + bsv[2], acc[i][3] + bsv[3]);
        float4 v1 = make_float4(acc[i][4] + bsv[4], acc[i][5] + bsv[5],
                                acc[i][6] + bsv[6], acc[i][7] + bsv[7]);
        *(float4*)(C + (size_t)r * N + col0 + tx * 4)      = v0;
        *(float4*)(C + (size_t)r * N + col0 + 64 + tx * 4) = v1;
    }
}

// ---------------- SGEMM half-height: BM=64, BN=128 (for the N=128 GEMM tail) ----
__global__ __launch_bounds__(256) void sgemm2h(
    const float* __restrict__ A,
    const float* __restrict__ B1, const float* __restrict__ B2,
    const float* __restrict__ bias1, const float* __restrict__ bias2,
    float* __restrict__ C, int M, int K, int halfN)
{
    __shared__ float As[2][8][64];
    __shared__ float Bs[2][8][128];
    const int N = 2 * halfN;
    int tid = threadIdx.x;
    int row0 = blockIdx.y * 64, col0 = blockIdx.x * 128;

    int aRow = tid >> 2, aCol = (tid & 3) * 2;
    int bRow = tid >> 5, bCol = (tid & 31) * 4;
    int gcol = col0 + bCol;
    const float* Bsrc = (gcol < halfN) ? B1 : B2;
    int bc = (gcol < halfN) ? gcol : gcol - halfN;

    int tx = tid & 15, ty = tid >> 4;   // ty 0..15
    float acc[4][8] = {};

    float2 av; float4 bv;
    {
        int r = row0 + aRow;
        av = (r < M) ? *(const float2*)(A + (size_t)r * K + aCol)
                     : make_float2(0.f, 0.f);
        bv = *(const float4*)(Bsrc + (size_t)bRow * halfN + bc);
        As[0][aCol + 0][aRow] = av.x; As[0][aCol + 1][aRow] = av.y;
        *(float4*)&Bs[0][bRow][bCol] = bv;
    }
    __syncthreads();

    int nk = K / 8;
    for (int kt = 0; kt < nk; kt++) {
        int buf = kt & 1;
        if (kt + 1 < nk) {
            int k0 = (kt + 1) * 8;
            int r = row0 + aRow;
            av = (r < M) ? *(const float2*)(A + (size_t)r * K + k0 + aCol)
                         : make_float2(0.f, 0.f);
            bv = *(const float4*)(Bsrc + (size_t)(k0 + bRow) * halfN + bc);
        }
#pragma unroll
        for (int k = 0; k < 8; k++) {
            float2 a0 = *(const float2*)&As[buf][k][ty * 2];
            float2 a1 = *(const float2*)&As[buf][k][ty * 2 + 32];
            float4 b0 = *(const float4*)&Bs[buf][k][tx * 4];
            float4 b1 = *(const float4*)&Bs[buf][k][tx * 4 + 64];
            float ar[4] = {a0.x, a0.y, a1.x, a1.y};
            float br[8] = {b0.x, b0.y, b0.z, b0.w, b1.x, b1.y, b1.z, b1.w};
#pragma unroll
            for (int i = 0; i < 4; i++)
#pragma unroll
                for (int j = 0; j < 8; j++) acc[i][j] += ar[i] * br[j];
        }
        if (kt + 1 < nk) {
            int nb = buf ^ 1;
            As[nb][aCol + 0][aRow] = av.x; As[nb][aCol + 1][aRow] = av.y;
            *(float4*)&Bs[nb][bRow][bCol] = bv;
        }
        __syncthreads();
    }

    float bsv[8];
#pragma unroll
    for (int j = 0; j < 8; j++) {
        int c = col0 + ((j < 4) ? tx * 4 + j : 64 + tx * 4 + (j - 4));
        bsv[j] = (c < halfN) ? bias1[c] : bias2[c - halfN];
    }
    const int rofs[4] = {ty * 2, ty * 2 + 1, ty * 2 + 32, ty * 2 + 33};
#pragma unroll
    for (int i = 0; i < 4; i++) {
        int r = row0 + rofs[i];
        if (r >= M) continue;
        float4 v0 = make_float4(acc[i][0] + bsv[0], acc[i][1] + bsv[1],
                                acc[i][2] + bsv[2], acc[i][3] + bsv[3]);
        float4 v1 = make_float4(acc[i][4] + bsv[4], acc[i][5] + bsv[5],
                                acc[i][6] + bsv[6], acc[i][7] + bsv[7]);
        *(float4*)(C + (size_t)r * N + col0 + tx * 4)      = v0;
        *(float4*)(C + (size_t)r * N + col0 + 64 + tx * 4) = v1;
    }
}

// ---------------- fused GAT layer 1: warp/node, 24 lanes x 8 contiguous ch -------
__global__ __launch_bounds__(256) void gat1_kernel(
    const float* __restrict__ We, const float* __restrict__ att,
    const float* __restrict__ bias)
{
    int node = blockIdx.x * 8 + (threadIdx.x >> 5);
    int lane = threadIdx.x & 31;
    if (node >= N_NODES) return;
    int beg = g_rowoff[node], end = g_rowoff[node + 1];
    int chb = (lane < 24) ? (lane << 3) : 0;

    const float4* xrp = (const float4*)(g_xw1 + (size_t)node * 384 + 192 + chb);
    float4 xr0 = xrp[0], xr1 = xrp[1];
    float4 We0 = *(const float4*)(We + chb),  We4 = *(const float4*)(We + chb + 4);
    float4 at0 = *(const float4*)(att + chb), at4 = *(const float4*)(att + chb + 4);

    float4 acc0 = make_float4(0.f, 0.f, 0.f, 0.f);
    float4 acc1 = make_float4(0.f, 0.f, 0.f, 0.f);
    float den = 0.f;

    int e = beg;
    int2 pr = make_int2(0, 0);
    if (e < end) pr = g_epack[e];
    while (e < end) {
        int e2 = e + 1;
        int2 pr2 = make_int2(0, 0);
        if (e2 < end) pr2 = g_epack[e2];
        int s = pr.x;
        float a = __int_as_float(pr.y);

        const float4* xlp = (const float4*)(g_xw1 + (size_t)s * 384 + chb);
        float4 x0 = xlp[0], x1 = xlp[1];

        float p;
        p  = at0.x * lrelu(fmaf(a, We0.x, x0.x + xr0.x));
        p += at0.y * lrelu(fmaf(a, We0.y, x0.y + xr0.y));
        p += at0.z * lrelu(fmaf(a, We0.z, x0.z + xr0.z));
        p += at0.w * lrelu(fmaf(a, We0.w, x0.w + xr0.w));
        p += at4.x * lrelu(fmaf(a, We4.x, x1.x + xr1.x));
        p += at4.y * lrelu(fmaf(a, We4.y, x1.y + xr1.y));
        p += at4.z * lrelu(fmaf(a, We4.z, x1.z + xr1.z));
        p += at4.w * lrelu(fmaf(a, We4.w, x1.w + xr1.w));
        // head-group (8 lanes) butterfly
        p += __shfl_xor_sync(0xffffffffu, p, 1);
        p += __shfl_xor_sync(0xffffffffu, p, 2);
        p += __shfl_xor_sync(0xffffffffu, p, 4);
        float w = __expf(p);
        den += w;
        acc0.x = fmaf(w, x0.x, acc0.x); acc0.y = fmaf(w, x0.y, acc0.y);
        acc0.z = fmaf(w, x0.z, acc0.z); acc0.w = fmaf(w, x0.w, acc0.w);
        acc1.x = fmaf(w, x1.x, acc1.x); acc1.y = fmaf(w, x1.y, acc1.y);
        acc1.z = fmaf(w, x1.z, acc1.z); acc1.w = fmaf(w, x1.w, acc1.w);

        pr = pr2; e = e2;
    }

    if (lane < 24) {
        float dinv = 1.f / (den + 1e-16f);
        float4 b0 = *(const float4*)(bias + chb);
        float4 b4 = *(const float4*)(bias + chb + 4);
        float4 o0, o1;
        o0.x = elu(fmaf(acc0.x, dinv, b0.x));
        o0.y = elu(fmaf(acc0.y, dinv, b0.y));
        o0.z = elu(fmaf(acc0.z, dinv, b0.z));
        o0.w = elu(fmaf(acc0.w, dinv, b0.w));
        o1.x = elu(fmaf(acc1.x, dinv, b4.x));
        o1.y = elu(fmaf(acc1.y, dinv, b4.y));
        o1.z = elu(fmaf(acc1.z, dinv, b4.z));
        o1.w = elu(fmaf(acc1.w, dinv, b4.w));
        float4* hp = (float4*)(g_h1 + (size_t)node * D1 + chb);
        hp[0] = o0; hp[1] = o1;
    }
}

// ---------------- fused GAT layer 2: warp/node, 2 edges/warp, 16 lanes x 4 ch ----
__global__ __launch_bounds__(256) void gat2_kernel(
    const float* __restrict__ We, const float* __restrict__ att,
    const float* __restrict__ bias, float* __restrict__ out)
{
    int node = blockIdx.x * 8 + (threadIdx.x >> 5);
    int lane = threadIdx.x & 31;
    if (node >= N_NODES) return;
    int beg = g_rowoff[node], end = g_rowoff[node + 1];
    int half = lane >> 4;
    int chb = (lane & 15) << 2;

    float4 xr  = *(const float4*)(g_xw2 + (size_t)node * 128 + 64 + chb);
    float4 Wev = *(const float4*)(We + chb);
    float4 atv = *(const float4*)(att + chb);

    float4 acc = make_float4(0.f, 0.f, 0.f, 0.f);
    float den = 0.f;

    int base = beg;
    int e = base + half;
    bool valid = (e < end) && (base < end);
    int2 pr = make_int2(0, 0);
    if (valid) pr = g_epack[e];
    while (base < end) {
        int base2 = base + 2;
        int e2 = base2 + half;
        bool v2 = (base2 < end) && (e2 < end);
        int2 pr2 = make_int2(0, 0);
        if (v2) pr2 = g_epack[e2];
        int s = pr.x;
        float a = __int_as_float(pr.y);

        float4 x = *(const float4*)(g_xw2 + (size_t)s * 128 + chb);
        float p;
        p  = atv.x * lrelu(fmaf(a, Wev.x, x.x + xr.x));
        p += atv.y * lrelu(fmaf(a, Wev.y, x.y + xr.y));
        p += atv.z * lrelu(fmaf(a, Wev.z, x.z + xr.z));
        p += atv.w * lrelu(fmaf(a, Wev.w, x.w + xr.w));
        // butterfly within 16-lane half
        p += __shfl_xor_sync(0xffffffffu, p, 1);
        p += __shfl_xor_sync(0xffffffffu, p, 2);
        p += __shfl_xor_sync(0xffffffffu, p, 4);
        p += __shfl_xor_sync(0xffffffffu, p, 8);
        float w = valid ? __expf(p) : 0.f;
        den += w;
        acc.x = fmaf(w, x.x, acc.x); acc.y = fmaf(w, x.y, acc.y);
        acc.z = fmaf(w, x.z, acc.z); acc.w = fmaf(w, x.w, acc.w);

        base = base2; pr = pr2; valid = v2;
    }

    // combine the two halves (same channel lives on lane and lane^16)
    den   += __shfl_xor_sync(0xffffffffu, den,   16);
    acc.x += __shfl_xor_sync(0xffffffffu, acc.x, 16);
    acc.y += __shfl_xor_sync(0xffffffffu, acc.y, 16);
    acc.z += __shfl_xor_sync(0xffffffffu, acc.z, 16);
    acc.w += __shfl_xor_sync(0xffffffffu, acc.w, 16);

    if (half == 0) {
        float dinv = 1.f / (den + 1e-16f);
        float4 bv = *(const float4*)(bias + chb);
        float4 o;
        o.x = elu(fmaf(acc.x, dinv, bv.x));
        o.y = elu(fmaf(acc.y, dinv, bv.y));
        o.z = elu(fmaf(acc.z, dinv, bv.z));
        o.w = elu(fmaf(acc.w, dinv, bv.w));
        *(float4*)(out + (size_t)node * OUT + chb) = o;
    }
}

// ---------------- launch ----------------
extern "C" void kernel_launch(void* const* d_in, const int* in_sizes, int n_in,
                              void* d_out, int out_size) {
    const float* x     = (const float*)d_in[0];
    const int*   eidx  = (const int*)d_in[1];
    const float* eattr = (const float*)d_in[2];
    const float* Wl1   = (const float*)d_in[3];
    const float* bl1   = (const float*)d_in[4];
    const float* Wr1   = (const float*)d_in[5];
    const float* br1   = (const float*)d_in[6];
    const float* We1   = (const float*)d_in[7];
    const float* att1  = (const float*)d_in[8];
    const float* bias1 = (const float*)d_in[9];
    const float* Wl2   = (const float*)d_in[10];
    const float* bl2   = (const float*)d_in[11];
    const float* Wr2   = (const float*)d_in[12];
    const float* br2   = (const float*)d_in[13];
    const float* We2   = (const float*)d_in[14];
    const float* att2  = (const float*)d_in[15];
    const float* bias2 = (const float*)d_in[16];
    float* out = (float*)d_out;

    static float* p_xw1 = nullptr;
    static float* p_h1  = nullptr;
    static float* p_xw2 = nullptr;
    if (!p_xw1) {
        cudaGetSymbolAddress((void**)&p_xw1, g_xw1);
        cudaGetSymbolAddress((void**)&p_h1,  g_h1);
        cudaGetSymbolAddress((void**)&p_xw2, g_xw2);
    }

    const int ET = (N_EDGES + 255) / 256;

    detect_kernel<<<1, 256>>>(eidx);                 // 1
    clear_cnt<<<NBLK, 256>>>();                      // 2
    hist_kernel<<<ET, 256>>>(eidx);                  // 3
    // layer 1 GEMM placed 4th so ncu captures it (independent of CSR build)
    {
        dim3 grid(3, (N_NODES + 127) / 128);
        sgemm2<<<grid, 256>>>(x, Wl1, Wr1, bl1, br1, p_xw1, N_NODES, F_IN, D1);  // 4
    }
    scanA<<<NBLK, 256>>>();                          // 5
    scanB<<<1, 256>>>();                             // 6
    scanC<<<NBLK, 256>>>();                          // 7
    scatter_kernel<<<ET, 256>>>(eidx, eattr);        // 8
    gat1_kernel<<<(N_NODES + 7) / 8, 256>>>(We1, att1, bias1);                   // 9
    {
        dim3 grid(1, (N_NODES + 63) / 64);
        sgemm2h<<<grid, 256>>>(p_h1, Wl2, Wr2, bl2, br2, p_xw2, N_NODES, D1, OUT); // 10
    }
    gat2_kernel<<<(N_NODES + 7) / 8, 256>>>(We2, att2, bias2, out);              // 11
}

// round 12
// speedup vs baseline: 1.0958x; 1.0656x over previous
#include <cuda_runtime.h>
#include <math.h>

#define N_NODES 50000
#define N_EDGES 800000
#define F_IN    128
#define HID     64
#define H1      3
#define D1      (H1*HID)        // 192
#define OUT     64
#define LRELU   0.2f
#define NBLK    ((N_NODES + 255) / 256)   // 196

// ---------------- scratch (device globals; no allocation allowed) ----------------
__device__ int   g_is64;
__device__ int   g_cnt[N_NODES];
__device__ int   g_bsum[256];
__device__ int   g_boff[256];
__device__ int   g_rowoff[N_NODES + 1];
__device__ int   g_cur[N_NODES];
__device__ int2  g_epack[N_EDGES];              // {src, float_bits(edge_attr)}
__device__ float g_xw1[(size_t)N_NODES * 384];  // [node][xl(192) | xr(192)]
__device__ float g_h1[(size_t)N_NODES * D1];
__device__ float g_xw2[(size_t)N_NODES * 128];  // [node][xl(64) | xr(64)]

// ---------------- helpers ----------------
__device__ __forceinline__ float lrelu(float v) { return v > 0.f ? v : LRELU * v; }
__device__ __forceinline__ float elu(float v)   { return v > 0.f ? v : expm1f(v); }

// packed f32x2: d = a*b + d  (exact same numerics as two scalar fmaf)
__device__ __forceinline__ void ffma2(unsigned long long& d,
                                      unsigned long long a,
                                      unsigned long long b) {
    asm("fma.rn.f32x2 %0, %1, %2, %3;" : "=l"(d) : "l"(a), "l"(b), "l"(d));
}
__device__ __forceinline__ unsigned long long dup2(float f) {
    unsigned long long d;
    asm("mov.b64 %0, {%1, %1};" : "=l"(d) : "f"(f));
    return d;
}
__device__ __forceinline__ float2 unpk(unsigned long long v) {
    float lo, hi;
    asm("mov.b64 {%0, %1}, %2;" : "=f"(lo), "=f"(hi) : "l"(v));
    return make_float2(lo, hi);
}

// ---------------- edge_index dtype detect ----------------
__global__ void detect_kernel(const int* __restrict__ p) {
    int acc = 0;
    for (int i = threadIdx.x; i < 2048; i += blockDim.x) acc |= p[2 * i + 1];
    int any = __syncthreads_or(acc);
    if (threadIdx.x == 0) g_is64 = (any == 0) ? 1 : 0;
}

__global__ void clear_cnt() {
    int i = blockIdx.x * blockDim.x + threadIdx.x;
    if (i < N_NODES) g_cnt[i] = 0;
}

__global__ void hist_kernel(const int* __restrict__ p) {
    int i = blockIdx.x * blockDim.x + threadIdx.x;
    if (i >= N_EDGES) return;
    int d = g_is64 ? p[2 * N_EDGES + 2 * i] : p[N_EDGES + i];
    atomicAdd(&g_cnt[d], 1);
}

__global__ void scanA() {
    __shared__ int sm[256];
    int i = blockIdx.x * 256 + threadIdx.x;
    sm[threadIdx.x] = (i < N_NODES) ? g_cnt[i] : 0;
    __syncthreads();
    for (int off = 128; off; off >>= 1) {
        if (threadIdx.x < off) sm[threadIdx.x] += sm[threadIdx.x + off];
        __syncthreads();
    }
    if (threadIdx.x == 0) g_bsum[blockIdx.x] = sm[0];
}

__global__ void scanB() {
    __shared__ int sm[256];
    int t = threadIdx.x;
    sm[t] = (t < NBLK) ? g_bsum[t] : 0;
    __syncthreads();
    for (int off = 1; off < 256; off <<= 1) {
        int v = (t >= off) ? sm[t - off] : 0;
        __syncthreads();
        sm[t] += v;
        __syncthreads();
    }
    if (t < NBLK) g_boff[t] = sm[t] - g_bsum[t];
}

__global__ void scanC() {
    __shared__ int sm[256];
    int t = threadIdx.x;
    int i = blockIdx.x * 256 + t;
    int c = (i < N_NODES) ? g_cnt[i] : 0;
    sm[t] = c;
    __syncthreads();
    for (int off = 1; off < 256; off <<= 1) {
        int v = (t >= off) ? sm[t - off] : 0;
        __syncthreads();
        sm[t] += v;
        __syncthreads();
    }
    if (i < N_NODES) {
        int start = g_boff[blockIdx.x] + sm[t] - c;
        g_rowoff[i] = start;
        g_cur[i] = start;
    }
    if (blockIdx.x == 0 && t == 0) g_rowoff[N_NODES] = N_EDGES;
}

__global__ void scatter_kernel(const int* __restrict__ p,
                               const float* __restrict__ eattr) {
    int i = blockIdx.x * blockDim.x + threadIdx.x;
    if (i >= N_EDGES) return;
    int s, d;
    if (g_is64) {
        s = p[2 * i];
        d = p[2 * N_EDGES + 2 * i];
    } else {
        s = p[i];
        d = p[N_EDGES + i];
    }
    int pos = atomicAdd(&g_cur[d], 1);
    g_epack[pos] = make_int2(s, __float_as_int(eattr[i]));
}

// ---------------- SGEMM (f32x2): C[M,2*halfN] = A @ [B1|B2] + [bias1|bias2] ----
// BM=BN=128, BK=8, 256 threads, 8x8 micro-tile via 4x8 packed-pair FFMA2.
__global__ __launch_bounds__(256, 2) void sgemm2(
    const float* __restrict__ A,
    const float* __restrict__ B1, const float* __restrict__ B2,
    const float* __restrict__ bias1, const float* __restrict__ bias2,
    float* __restrict__ C, int M, int K, int halfN)
{
    __shared__ float As[2][8][128];
    __shared__ float Bs[2][8][128];
    const int N = 2 * halfN;
    int tid = threadIdx.x;
    int row0 = blockIdx.y * 128, col0 = blockIdx.x * 128;

    int aRow = tid >> 1, aCol = (tid & 1) * 4;
    int bRow = tid >> 5, bCol = (tid & 31) * 4;
    int gcol = col0 + bCol;
    const float* Bsrc = (gcol < halfN) ? B1 : B2;
    int bc = (gcol < halfN) ? gcol : gcol - halfN;

    int tx = tid & 15, ty = tid >> 4;
    // acc2[ip][j]: ip = a-row-pair (rows ty*4 + (ip&1)*2 + (ip>>1)*64, +1), j = col
    unsigned long long acc2[4][8] = {};

    float4 av, bv;
    {
        int r = row0 + aRow;
        av = (r < M) ? *(const float4*)(A + (size_t)r * K + aCol)
                     : make_float4(0.f, 0.f, 0.f, 0.f);
        bv = *(const float4*)(Bsrc + (size_t)bRow * halfN + bc);
        As[0][aCol + 0][aRow] = av.x; As[0][aCol + 1][aRow] = av.y;
        As[0][aCol + 2][aRow] = av.z; As[0][aCol + 3][aRow] = av.w;
        *(float4*)&Bs[0][bRow][bCol] = bv;
    }
    __syncthreads();

    int nk = K / 8;
    for (int kt = 0; kt < nk; kt++) {
        int buf = kt & 1;
        if (kt + 1 < nk) {
            int k0 = (kt + 1) * 8;
            int r = row0 + aRow;
            av = (r < M) ? *(const float4*)(A + (size_t)r * K + k0 + aCol)
                         : make_float4(0.f, 0.f, 0.f, 0.f);
            bv = *(const float4*)(Bsrc + (size_t)(k0 + bRow) * halfN + bc);
        }
#pragma unroll
        for (int k = 0; k < 8; k++) {
            // a-pairs directly from smem (adjacent rows adjacent in smem)
            ulonglong2 paA = *(const ulonglong2*)&As[buf][k][ty * 4];
            ulonglong2 paB = *(const ulonglong2*)&As[buf][k][ty * 4 + 64];
            float4 b0 = *(const float4*)&Bs[buf][k][tx * 4];
            float4 b1 = *(const float4*)&Bs[buf][k][tx * 4 + 64];
            unsigned long long pa[4] = {paA.x, paA.y, paB.x, paB.y};
            unsigned long long bb[8] = {
                dup2(b0.x), dup2(b0.y), dup2(b0.z), dup2(b0.w),
                dup2(b1.x), dup2(b1.y), dup2(b1.z), dup2(b1.w)};
#pragma unroll
            for (int ip = 0; ip < 4; ip++)
#pragma unroll
                for (int j = 0; j < 8; j++) ffma2(acc2[ip][j], pa[ip], bb[j]);
        }
        if (kt + 1 < nk) {
            int nb = buf ^ 1;
            As[nb][aCol + 0][aRow] = av.x; As[nb][aCol + 1][aRow] = av.y;
            As[nb][aCol + 2][aRow] = av.z; As[nb][aCol + 3][aRow] = av.w;
            *(float4*)&Bs[nb][bRow][bCol] = bv;
        }
        __syncthreads();
    }

    float bsv[8];
#pragma unroll
    for (int j = 0; j < 8; j++) {
        int c = col0 + ((j < 4) ? tx * 4 + j : 64 + tx * 4 + (j - 4));
        bsv[j] = (c < halfN) ? bias1[c] : bias2[c - halfN];
    }
#pragma unroll
    for (int ip = 0; ip < 4; ip++) {
        int rbase = row0 + ty * 4 + (ip & 1) * 2 + (ip >> 1) * 64;
        float2 col_v[8];
#pragma unroll
        for (int j = 0; j < 8; j++) col_v[j] = unpk(acc2[ip][j]);
#pragma unroll
        for (int h = 0; h < 2; h++) {
            int r = rbase + h;
            if (r >= M) continue;
            float v[8];
#pragma unroll
            for (int j = 0; j < 8; j++)
                v[j] = ((h == 0) ? col_v[j].x : col_v[j].y) + bsv[j];
            *(float4*)(C + (size_t)r * N + col0 + tx * 4) =
                make_float4(v[0], v[1], v[2], v[3]);
            *(float4*)(C + (size_t)r * N + col0 + 64 + tx * 4) =
                make_float4(v[4], v[5], v[6], v[7]);
        }
    }
}

// ---------------- SGEMM half-height (f32x2): BM=64, BN=128 ----------------------
__global__ __launch_bounds__(256) void sgemm2h(
    const float* __restrict__ A,
    const float* __restrict__ B1, const float* __restrict__ B2,
    const float* __restrict__ bias1, const float* __restrict__ bias2,
    float* __restrict__ C, int M, int K, int halfN)
{
    __shared__ float As[2][8][64];
    __shared__ float Bs[2][8][128];
    const int N = 2 * halfN;
    int tid = threadIdx.x;
    int row0 = blockIdx.y * 64, col0 = blockIdx.x * 128;

    int aRow = tid >> 2, aCol = (tid & 3) * 2;
    int bRow = tid >> 5, bCol = (tid & 31) * 4;
    int gcol = col0 + bCol;
    const float* Bsrc = (gcol < halfN) ? B1 : B2;
    int bc = (gcol < halfN) ? gcol : gcol - halfN;

    int tx = tid & 15, ty = tid >> 4;   // ty 0..15
    // acc2[ip][j]: ip=0 rows {ty*2, ty*2+1}; ip=1 rows {32+ty*2, 32+ty*2+1}
    unsigned long long acc2[2][8] = {};

    float2 av; float4 bv;
    {
        int r = row0 + aRow;
        av = (r < M) ? *(const float2*)(A + (size_t)r * K + aCol)
                     : make_float2(0.f, 0.f);
        bv = *(const float4*)(Bsrc + (size_t)bRow * halfN + bc);
        As[0][aCol + 0][aRow] = av.x; As[0][aCol + 1][aRow] = av.y;
        *(float4*)&Bs[0][bRow][bCol] = bv;
    }
    __syncthreads();

    int nk = K / 8;
    for (int kt = 0; kt < nk; kt++) {
        int buf = kt & 1;
        if (kt + 1 < nk) {
            int k0 = (kt + 1) * 8;
            int r = row0 + aRow;
            av = (r < M) ? *(const float2*)(A + (size_t)r * K + k0 + aCol)
                         : make_float2(0.f, 0.f);
            bv = *(const float4*)(Bsrc + (size_t)(k0 + bRow) * halfN + bc);
        }
#pragma unroll
        for (int k = 0; k < 8; k++) {
            unsigned long long pa0 = *(const unsigned long long*)&As[buf][k][ty * 2];
            unsigned long long pa1 = *(const unsigned long long*)&As[buf][k][ty * 2 + 32];
            float4 b0 = *(const float4*)&Bs[buf][k][tx * 4];
            float4 b1 = *(const float4*)&Bs[buf][k][tx * 4 + 64];
            unsigned long long bb[8] = {
                dup2(b0.x), dup2(b0.y), dup2(b0.z), dup2(b0.w),
                dup2(b1.x), dup2(b1.y), dup2(b1.z), dup2(b1.w)};
#pragma unroll
            for (int j = 0; j < 8; j++) ffma2(acc2[0][j], pa0, bb[j]);
#pragma unroll
            for (int j = 0; j < 8; j++) ffma2(acc2[1][j], pa1, bb[j]);
        }
        if (kt + 1 < nk) {
            int nb = buf ^ 1;
            As[nb][aCol + 0][aRow] = av.x; As[nb][aCol + 1][aRow] = av.y;
            *(float4*)&Bs[nb][bRow][bCol] = bv;
        }
        __syncthreads();
    }

    float bsv[8];
#pragma unroll
    for (int j = 0; j < 8; j++) {
        int c = col0 + ((j < 4) ? tx * 4 + j : 64 + tx * 4 + (j - 4));
        bsv[j] = (c < halfN) ? bias1[c] : bias2[c - halfN];
    }
#pragma unroll
    for (int ip = 0; ip < 2; ip++) {
        int rbase = row0 + ty * 2 + ip * 32;
        float2 col_v[8];
#pragma unroll
        for (int j = 0; j < 8; j++) col_v[j] = unpk(acc2[ip][j]);
#pragma unroll
        for (int h = 0; h < 2; h++) {
            int r = rbase + h;
            if (r >= M) continue;
            float v[8];
#pragma unroll
            for (int j = 0; j < 8; j++)
                v[j] = ((h == 0) ? col_v[j].x : col_v[j].y) + bsv[j];
            *(float4*)(C + (size_t)r * N + col0 + tx * 4) =
                make_float4(v[0], v[1], v[2], v[3]);
            *(float4*)(C + (size_t)r * N + col0 + 64 + tx * 4) =
                make_float4(v[4], v[5], v[6], v[7]);
        }
    }
}

// ---------------- fused GAT layer 1: warp/node, 24 lanes x 8 contiguous ch -------
__global__ __launch_bounds__(256) void gat1_kernel(
    const float* __restrict__ We, const float* __restrict__ att,
    const float* __restrict__ bias)
{
    int node = blockIdx.x * 8 + (threadIdx.x >> 5);
    int lane = threadIdx.x & 31;
    if (node >= N_NODES) return;
    int beg = g_rowoff[node], end = g_rowoff[node + 1];
    int chb = (lane < 24) ? (lane << 3) : 0;

    const float4* xrp = (const float4*)(g_xw1 + (size_t)node * 384 + 192 + chb);
    float4 xr0 = xrp[0], xr1 = xrp[1];
    float4 We0 = *(const float4*)(We + chb),  We4 = *(const float4*)(We + chb + 4);
    float4 at0 = *(const float4*)(att + chb), at4 = *(const float4*)(att + chb + 4);

    float4 acc0 = make_float4(0.f, 0.f, 0.f, 0.f);
    float4 acc1 = make_float4(0.f, 0.f, 0.f, 0.f);
    float den = 0.f;

    int e = beg;
    int2 pr = make_int2(0, 0);
    if (e < end) pr = g_epack[e];
    while (e < end) {
        int e2 = e + 1;
        int2 pr2 = make_int2(0, 0);
        if (e2 < end) pr2 = g_epack[e2];
        int s = pr.x;
        float a = __int_as_float(pr.y);

        const float4* xlp = (const float4*)(g_xw1 + (size_t)s * 384 + chb);
        float4 x0 = xlp[0], x1 = xlp[1];

        float p;
        p  = at0.x * lrelu(fmaf(a, We0.x, x0.x + xr0.x));
        p += at0.y * lrelu(fmaf(a, We0.y, x0.y + xr0.y));
        p += at0.z * lrelu(fmaf(a, We0.z, x0.z + xr0.z));
        p += at0.w * lrelu(fmaf(a, We0.w, x0.w + xr0.w));
        p += at4.x * lrelu(fmaf(a, We4.x, x1.x + xr1.x));
        p += at4.y * lrelu(fmaf(a, We4.y, x1.y + xr1.y));
        p += at4.z * lrelu(fmaf(a, We4.z, x1.z + xr1.z));
        p += at4.w * lrelu(fmaf(a, We4.w, x1.w + xr1.w));
        p += __shfl_xor_sync(0xffffffffu, p, 1);
        p += __shfl_xor_sync(0xffffffffu, p, 2);
        p += __shfl_xor_sync(0xffffffffu, p, 4);
        float w = __expf(p);
        den += w;
        acc0.x = fmaf(w, x0.x, acc0.x); acc0.y = fmaf(w, x0.y, acc0.y);
        acc0.z = fmaf(w, x0.z, acc0.z); acc0.w = fmaf(w, x0.w, acc0.w);
        acc1.x = fmaf(w, x1.x, acc1.x); acc1.y = fmaf(w, x1.y, acc1.y);
        acc1.z = fmaf(w, x1.z, acc1.z); acc1.w = fmaf(w, x1.w, acc1.w);

        pr = pr2; e = e2;
    }

    if (lane < 24) {
        float dinv = 1.f / (den + 1e-16f);
        float4 b0 = *(const float4*)(bias + chb);
        float4 b4 = *(const float4*)(bias + chb + 4);
        float4 o0, o1;
        o0.x = elu(fmaf(acc0.x, dinv, b0.x));
        o0.y = elu(fmaf(acc0.y, dinv, b0.y));
        o0.z = elu(fmaf(acc0.z, dinv, b0.z));
        o0.w = elu(fmaf(acc0.w, dinv, b0.w));
        o1.x = elu(fmaf(acc1.x, dinv, b4.x));
        o1.y = elu(fmaf(acc1.y, dinv, b4.y));
        o1.z = elu(fmaf(acc1.z, dinv, b4.z));
        o1.w = elu(fmaf(acc1.w, dinv, b4.w));
        float4* hp = (float4*)(g_h1 + (size_t)node * D1 + chb);
        hp[0] = o0; hp[1] = o1;
    }
}

// ---------------- fused GAT layer 2: warp/node, 2 edges/warp, 16 lanes x 4 ch ----
__global__ __launch_bounds__(256) void gat2_kernel(
    const float* __restrict__ We, const float* __restrict__ att,
    const float* __restrict__ bias, float* __restrict__ out)
{
    int node = blockIdx.x * 8 + (threadIdx.x >> 5);
    int lane = threadIdx.x & 31;
    if (node >= N_NODES) return;
    int beg = g_rowoff[node], end = g_rowoff[node + 1];
    int half = lane >> 4;
    int chb = (lane & 15) << 2;

    float4 xr  = *(const float4*)(g_xw2 + (size_t)node * 128 + 64 + chb);
    float4 Wev = *(const float4*)(We + chb);
    float4 atv = *(const float4*)(att + chb);

    float4 acc = make_float4(0.f, 0.f, 0.f, 0.f);
    float den = 0.f;

    int base = beg;
    int e = base + half;
    bool valid = (e < end) && (base < end);
    int2 pr = make_int2(0, 0);
    if (valid) pr = g_epack[e];
    while (base < end) {
        int base2 = base + 2;
        int e2 = base2 + half;
        bool v2 = (base2 < end) && (e2 < end);
        int2 pr2 = make_int2(0, 0);
        if (v2) pr2 = g_epack[e2];
        int s = pr.x;
        float a = __int_as_float(pr.y);

        float4 x = *(const float4*)(g_xw2 + (size_t)s * 128 + chb);
        float p;
        p  = atv.x * lrelu(fmaf(a, Wev.x, x.x + xr.x));
        p += atv.y * lrelu(fmaf(a, Wev.y, x.y + xr.y));
        p += atv.z * lrelu(fmaf(a, Wev.z, x.z + xr.z));
        p += atv.w * lrelu(fmaf(a, Wev.w, x.w + xr.w));
        p += __shfl_xor_sync(0xffffffffu, p, 1);
        p += __shfl_xor_sync(0xffffffffu, p, 2);
        p += __shfl_xor_sync(0xffffffffu, p, 4);
        p += __shfl_xor_sync(0xffffffffu, p, 8);
        float w = valid ? __expf(p) : 0.f;
        den += w;
        acc.x = fmaf(w, x.x, acc.x); acc.y = fmaf(w, x.y, acc.y);
        acc.z = fmaf(w, x.z, acc.z); acc.w = fmaf(w, x.w, acc.w);

        base = base2; pr = pr2; valid = v2;
    }

    den   += __shfl_xor_sync(0xffffffffu, den,   16);
    acc.x += __shfl_xor_sync(0xffffffffu, acc.x, 16);
    acc.y += __shfl_xor_sync(0xffffffffu, acc.y, 16);
    acc.z += __shfl_xor_sync(0xffffffffu, acc.z, 16);
    acc.w += __shfl_xor_sync(0xffffffffu, acc.w, 16);

    if (half == 0) {
        float dinv = 1.f / (den + 1e-16f);
        float4 bv = *(const float4*)(bias + chb);
        float4 o;
        o.x = elu(fmaf(acc.x, dinv, bv.x));
        o.y = elu(fmaf(acc.y, dinv, bv.y));
        o.z = elu(fmaf(acc.z, dinv, bv.z));
        o.w = elu(fmaf(acc.w, dinv, bv.w));
        *(float4*)(out + (size_t)node * OUT + chb) = o;
    }
}

// ---------------- launch ----------------
extern "C" void kernel_launch(void* const* d_in, const int* in_sizes, int n_in,
                              void* d_out, int out_size) {
    const float* x     = (const float*)d_in[0];
    const int*   eidx  = (const int*)d_in[1];
    const float* eattr = (const float*)d_in[2];
    const float* Wl1   = (const float*)d_in[3];
    const float* bl1   = (const float*)d_in[4];
    const float* Wr1   = (const float*)d_in[5];
    const float* br1   = (const float*)d_in[6];
    const float* We1   = (const float*)d_in[7];
    const float* att1  = (const float*)d_in[8];
    const float* bias1 = (const float*)d_in[9];
    const float* Wl2   = (const float*)d_in[10];
    const float* bl2   = (const float*)d_in[11];
    const float* Wr2   = (const float*)d_in[12];
    const float* br2   = (const float*)d_in[13];
    const float* We2   = (const float*)d_in[14];
    const float* att2  = (const float*)d_in[15];
    const float* bias2 = (const float*)d_in[16];
    float* out = (float*)d_out;

    static float* p_xw1 = nullptr;
    static float* p_h1  = nullptr;
    static float* p_xw2 = nullptr;
    if (!p_xw1) {
        cudaGetSymbolAddress((void**)&p_xw1, g_xw1);
        cudaGetSymbolAddress((void**)&p_h1,  g_h1);
        cudaGetSymbolAddress((void**)&p_xw2, g_xw2);
    }

    const int ET = (N_EDGES + 255) / 256;

    detect_kernel<<<1, 256>>>(eidx);                 // 1
    clear_cnt<<<NBLK, 256>>>();                      // 2
    hist_kernel<<<ET, 256>>>(eidx);                  // 3
    // layer 1 GEMM placed 4th so ncu captures it
    {
        dim3 grid(3, (N_NODES + 127) / 128);
        sgemm2<<<grid, 256>>>(x, Wl1, Wr1, bl1, br1, p_xw1, N_NODES, F_IN, D1);  // 4
    }
    scanA<<<NBLK, 256>>>();                          // 5
    scanB<<<1, 256>>>();                             // 6
    scanC<<<NBLK, 256>>>();                          // 7
    scatter_kernel<<<ET, 256>>>(eidx, eattr);        // 8
    gat1_kernel<<<(N_NODES + 7) / 8, 256>>>(We1, att1, bias1);                   // 9
    {
        dim3 grid(1, (N_NODES + 63) / 64);
        sgemm2h<<<grid, 256>>>(p_h1, Wl2, Wr2, bl2, br2, p_xw2, N_NODES, D1, OUT); // 10
    }
    gat2_kernel<<<(N_NODES + 7) / 8, 256>>>(We2, att2, bias2, out);              // 11
}